// round 3
// baseline (speedup 1.0000x reference)
#include <cuda_runtime.h>

#define NN 10000
#define EE 320000

__device__ float g_b1[(size_t)NN*256*64];   // conv1 out (also conv3 out)
__device__ float g_b0[(size_t)NN*64*64];    // conv2 out (also conv4 out)
__device__ float g_cf[NN*64];
__device__ float g_nA[NN*64];
__device__ float g_nB[NN*64];
__device__ float g_agg[NN*64];
__device__ float g_edge[(size_t)EE*64];

// ================= fused conv0(3->64) + conv1(64->64) per node-quadrant ======
__global__ void __launch_bounds__(256, 1) k_conv01(const float* __restrict__ crop,
    const float* __restrict__ w0, const float* __restrict__ b0_,
    const float* __restrict__ w1, const float* __restrict__ b1_,
    float* __restrict__ out) {
    extern __shared__ float sm[];
    float* w0s = sm;             // 768  [(c*4+p)*64 + oc]
    float* b0s = w0s + 768;      // 64
    float* w1s = b0s + 64;       // 16384 [(p*64+ic)*64 + oc]
    float* b1s = w1s + 16384;    // 64
    float* sIn = b1s + 64;       // 3*32*33 = 3168
    float* sA  = sIn + 3168;     // 256*65 = 16640 (conv0 out, [sp][ic] stride 65)

    const int t = threadIdx.x;
    const int n = blockIdx.x >> 2;
    const int q = blockIdx.x & 3;
    const int qy = q >> 1, qx = q & 1;

    for (int i = t; i < 768; i += 256) {
        int oc = i / 12, r = i - oc * 12;
        w0s[r * 64 + oc] = w0[i];
    }
    for (int i = t; i < 16384; i += 256) {
        int oc = i >> 8, r = i & 255, ic = r >> 2, p = r & 3;
        w1s[(p * 64 + ic) * 64 + oc] = w1[i];
    }
    if (t < 64) { b0s[t] = b0_[t]; b1s[t] = b1_[t]; }
    // input quadrant 32x32x3
    for (int e = t * 4; e < 3072; e += 1024) {
        int c = e >> 10, r = e & 1023, y = r >> 5, x = r & 31;
        float4 v = *(const float4*)&crop[(((size_t)n * 3 + c) * 64 + qy * 32 + y) * 64 + qx * 32 + x];
        float* d = &sIn[c * 1056 + y * 33 + x];
        d[0] = v.x; d[1] = v.y; d[2] = v.z; d[3] = v.w;
    }
    __syncthreads();

    // conv0: 256 sp x 64 oc, each thread: one sp, 4 oc, 16 iters
    #pragma unroll
    for (int it = 0; it < 16; it++) {
        int i = it * 256 + t;
        int sp = i >> 4, ocg = i & 15;
        int oy = sp >> 4, ox = sp & 15;
        float4 acc = *(const float4*)&b0s[ocg * 4];
        #pragma unroll
        for (int c = 0; c < 3; c++) {
            const float* ip = &sIn[c * 1056 + (2 * oy) * 33 + 2 * ox];
            #pragma unroll
            for (int p = 0; p < 4; p++) {
                float a = ip[(p >> 1) * 33 + (p & 1)];
                float4 w = *(const float4*)&w0s[(c * 4 + p) * 64 + ocg * 4];
                acc.x += a * w.x; acc.y += a * w.y; acc.z += a * w.z; acc.w += a * w.w;
            }
        }
        float* d = &sA[sp * 65 + ocg * 4];
        d[0] = fmaxf(acc.x, 0.f); d[1] = fmaxf(acc.y, 0.f);
        d[2] = fmaxf(acc.z, 0.f); d[3] = fmaxf(acc.w, 0.f);
    }
    __syncthreads();

    // conv1 GEMM: M=64 (8x8), N=64, K=256. 2 rows x 8 cols per thread.
    const int tr = t >> 3, tc = t & 7;
    const int r0 = 2 * tr, r1 = r0 + 1;
    const int oy0 = r0 >> 3, ox0 = r0 & 7;
    const int oy1 = r1 >> 3, ox1 = r1 & 7;
    float acc0[8], acc1[8];
    {
        float4 ba = *(const float4*)&b1s[tc * 8];
        float4 bb = *(const float4*)&b1s[tc * 8 + 4];
        acc0[0]=ba.x;acc0[1]=ba.y;acc0[2]=ba.z;acc0[3]=ba.w;
        acc0[4]=bb.x;acc0[5]=bb.y;acc0[6]=bb.z;acc0[7]=bb.w;
        #pragma unroll
        for (int j = 0; j < 8; j++) acc1[j] = acc0[j];
    }
    #pragma unroll
    for (int p = 0; p < 4; p++) {
        const int ky = p >> 1, kx = p & 1;
        const float* a0 = &sA[((2 * oy0 + ky) * 16 + 2 * ox0 + kx) * 65];
        const float* a1 = &sA[((2 * oy1 + ky) * 16 + 2 * ox1 + kx) * 65];
        const float* wp = &w1s[p * 4096 + tc * 8];
        #pragma unroll 8
        for (int k = 0; k < 64; k++) {
            float v0 = a0[k], v1 = a1[k];
            float4 wa = *(const float4*)&wp[k * 64];
            float4 wb = *(const float4*)&wp[k * 64 + 4];
            acc0[0]+=v0*wa.x; acc0[1]+=v0*wa.y; acc0[2]+=v0*wa.z; acc0[3]+=v0*wa.w;
            acc0[4]+=v0*wb.x; acc0[5]+=v0*wb.y; acc0[6]+=v0*wb.z; acc0[7]+=v0*wb.w;
            acc1[0]+=v1*wa.x; acc1[1]+=v1*wa.y; acc1[2]+=v1*wa.z; acc1[3]+=v1*wa.w;
            acc1[4]+=v1*wb.x; acc1[5]+=v1*wb.y; acc1[6]+=v1*wb.z; acc1[7]+=v1*wb.w;
        }
    }
    const int gsp0 = (qy * 8 + oy0) * 16 + qx * 8 + ox0;
    const int gsp1 = (qy * 8 + oy1) * 16 + qx * 8 + ox1;
    float* o0 = &out[((size_t)n * 256 + gsp0) * 64 + tc * 8];
    float* o1 = &out[((size_t)n * 256 + gsp1) * 64 + tc * 8];
    float4 v;
    v.x=fmaxf(acc0[0],0.f); v.y=fmaxf(acc0[1],0.f); v.z=fmaxf(acc0[2],0.f); v.w=fmaxf(acc0[3],0.f);
    *(float4*)o0 = v;
    v.x=fmaxf(acc0[4],0.f); v.y=fmaxf(acc0[5],0.f); v.z=fmaxf(acc0[6],0.f); v.w=fmaxf(acc0[7],0.f);
    *(float4*)(o0+4) = v;
    v.x=fmaxf(acc1[0],0.f); v.y=fmaxf(acc1[1],0.f); v.z=fmaxf(acc1[2],0.f); v.w=fmaxf(acc1[3],0.f);
    *(float4*)o1 = v;
    v.x=fmaxf(acc1[4],0.f); v.y=fmaxf(acc1[5],0.f); v.z=fmaxf(acc1[6],0.f); v.w=fmaxf(acc1[7],0.f);
    *(float4*)(o1+4) = v;
}

// ================== generic conv 64->64 k2s2, 128-row tiles, 4x8 per thread ==
__global__ void __launch_bounds__(256, 2) k_conv(const float* __restrict__ in,
    float* __restrict__ out, const float* __restrict__ w, const float* __restrict__ b,
    int so_bits, int M) {
    extern __shared__ float sm[];
    float* Ws = sm;            // 16384 [(p*64+ic)*64+oc]
    float* Bs = Ws + 16384;    // 64
    float* As = Bs + 64;       // 128*65
    const int t = threadIdx.x;
    const int Rbase = blockIdx.x * 128;
    for (int i = t; i < 16384; i += 256) {
        int oc = i >> 8, r = i & 255, ic = r >> 2, p = r & 3;
        Ws[(p * 64 + ic) * 64 + oc] = w[i];
    }
    if (t < 64) Bs[t] = b[t];
    const int S_out = 1 << so_bits, S_in = S_out * 2, so2 = 2 * so_bits;
    const int tr = t >> 3, tc = t & 7;
    const float* ar[4];
    #pragma unroll
    for (int i = 0; i < 4; i++) ar[i] = &As[(tr * 4 + i) * 65];
    float acc[4][8];
    for (int p = 0; p < 4; p++) {
        __syncthreads();
        const int ky = p >> 1, kx = p & 1;
        for (int e = t * 4; e < 8192; e += 1024) {
            int row = e >> 6, c4 = e & 63;
            int R = Rbase + row;
            float4 vv = make_float4(0.f, 0.f, 0.f, 0.f);
            if (R < M) {
                int n = R >> so2, sp = R & (S_out * S_out - 1);
                int oy = sp >> so_bits, ox = sp & (S_out - 1);
                vv = *(const float4*)&in[(((size_t)n * S_in + 2 * oy + ky) * S_in + 2 * ox + kx) * 64 + c4];
            }
            float* d = &As[row * 65 + c4];
            d[0] = vv.x; d[1] = vv.y; d[2] = vv.z; d[3] = vv.w;
        }
        __syncthreads();
        if (p == 0) {
            float4 ba = *(const float4*)&Bs[tc * 8];
            float4 bb = *(const float4*)&Bs[tc * 8 + 4];
            #pragma unroll
            for (int i = 0; i < 4; i++) {
                acc[i][0]=ba.x;acc[i][1]=ba.y;acc[i][2]=ba.z;acc[i][3]=ba.w;
                acc[i][4]=bb.x;acc[i][5]=bb.y;acc[i][6]=bb.z;acc[i][7]=bb.w;
            }
        }
        const float* wp = &Ws[p * 4096 + tc * 8];
        #pragma unroll 8
        for (int k = 0; k < 64; k++) {
            float4 wa = *(const float4*)&wp[k * 64];
            float4 wb = *(const float4*)&wp[k * 64 + 4];
            #pragma unroll
            for (int i = 0; i < 4; i++) {
                float a = ar[i][k];
                acc[i][0]+=a*wa.x; acc[i][1]+=a*wa.y; acc[i][2]+=a*wa.z; acc[i][3]+=a*wa.w;
                acc[i][4]+=a*wb.x; acc[i][5]+=a*wb.y; acc[i][6]+=a*wb.z; acc[i][7]+=a*wb.w;
            }
        }
    }
    #pragma unroll
    for (int i = 0; i < 4; i++) {
        int R = Rbase + tr * 4 + i;
        if (R < M) {
            float4 v;
            v.x=fmaxf(acc[i][0],0.f); v.y=fmaxf(acc[i][1],0.f);
            v.z=fmaxf(acc[i][2],0.f); v.w=fmaxf(acc[i][3],0.f);
            *(float4*)&out[(size_t)R * 64 + tc * 8] = v;
            v.x=fmaxf(acc[i][4],0.f); v.y=fmaxf(acc[i][5],0.f);
            v.z=fmaxf(acc[i][6],0.f); v.w=fmaxf(acc[i][7],0.f);
            *(float4*)&out[(size_t)R * 64 + tc * 8 + 4] = v;
        }
    }
}

// --------------------------------------------- node_update: [x|cf]@W + LN
__global__ void __launch_bounds__(256) k_nodeup(const float* __restrict__ x,
    const float* __restrict__ cf, const float* __restrict__ w, const float* __restrict__ b,
    const float* __restrict__ g, const float* __restrict__ be, float* __restrict__ out) {
    extern __shared__ float sm[];
    float* Ws = sm;
    float* Bs = Ws + 6144; float* Gs = Bs + 64; float* BEs = Gs + 64;
    float* mu = BEs + 64; float* rs = mu + 64;
    float* As = rs + 64;      // 64*100
    float* Hs = As + 6400;    // 64*68
    int t = threadIdx.x;
    int Rbase = blockIdx.x * 64;
    for (int i = t; i < 6144; i += 256) Ws[i] = w[i];
    if (t < 64) { Bs[t]=b[t]; Gs[t]=g[t]; BEs[t]=be[t]; }
    for (int e = t; e < 2048; e += 256) {
        int row = e >> 5, c = e & 31, nd = Rbase + row;
        As[row * 100 + c] = (nd < NN) ? x[nd * 32 + c] : 0.f;
    }
    for (int e = t; e < 4096; e += 256) {
        int row = e >> 6, c = e & 63, nd = Rbase + row;
        As[row * 100 + 32 + c] = (nd < NN) ? cf[nd * 64 + c] : 0.f;
    }
    __syncthreads();
    int tr = t >> 4, tc = t & 15;
    float acc[4][4];
    float4 b4 = *(const float4*)&Bs[tc * 4];
    #pragma unroll
    for (int i = 0; i < 4; i++) { acc[i][0]=b4.x; acc[i][1]=b4.y; acc[i][2]=b4.z; acc[i][3]=b4.w; }
    for (int k = 0; k < 96; k++) {
        float4 w4 = *(const float4*)&Ws[k * 64 + tc * 4];
        #pragma unroll
        for (int i = 0; i < 4; i++) {
            float a = As[(tr * 4 + i) * 100 + k];
            acc[i][0] += a*w4.x; acc[i][1] += a*w4.y; acc[i][2] += a*w4.z; acc[i][3] += a*w4.w;
        }
    }
    #pragma unroll
    for (int i = 0; i < 4; i++) {
        float4 r; r.x=fmaxf(acc[i][0],0.f); r.y=fmaxf(acc[i][1],0.f);
        r.z=fmaxf(acc[i][2],0.f); r.w=fmaxf(acc[i][3],0.f);
        *(float4*)&Hs[(tr * 4 + i) * 68 + tc * 4] = r;
    }
    __syncthreads();
    if (t < 64) {
        float s = 0.f, sq = 0.f;
        for (int c = 0; c < 64; c++) { float v = Hs[t * 68 + c]; s += v; sq += v * v; }
        float m = s * (1.f / 64.f);
        mu[t] = m; rs[t] = rsqrtf(sq * (1.f / 64.f) - m * m + 1e-5f);
    }
    __syncthreads();
    for (int i = t; i < 4096; i += 256) {
        int r = i >> 6, c = i & 63, nd = Rbase + r;
        if (nd < NN) out[nd * 64 + c] = (Hs[r * 68 + c] - mu[r]) * rs[r] * Gs[c] + BEs[c];
    }
}

// --------------------------------------------- edge_update: ea@W + LN
__global__ void __launch_bounds__(256) k_edgeup(const float* __restrict__ ea,
    const float* __restrict__ w, const float* __restrict__ b,
    const float* __restrict__ g, const float* __restrict__ be, float* __restrict__ out) {
    __shared__ float Ws[384], Bs[64], Gs[64], BEs[64], Aa[64][8], Hs[64][68], mu[64], rs[64];
    int t = threadIdx.x;
    int ebase = blockIdx.x * 64;
    for (int i = t; i < 384; i += 256) Ws[i] = w[i];
    if (t < 64) { Bs[t]=b[t]; Gs[t]=g[t]; BEs[t]=be[t]; }
    for (int e = t; e < 384; e += 256) {
        int row = e / 6, k = e - row * 6;
        Aa[row][k] = ea[(size_t)(ebase + row) * 6 + k];
    }
    __syncthreads();
    int r = t >> 2, cg = (t & 3) * 16;
    float a0=Aa[r][0],a1=Aa[r][1],a2=Aa[r][2],a3=Aa[r][3],a4=Aa[r][4],a5=Aa[r][5];
    #pragma unroll
    for (int j = 0; j < 16; j++) {
        int c = cg + j;
        float h = Bs[c] + a0*Ws[c] + a1*Ws[64+c] + a2*Ws[128+c] + a3*Ws[192+c] + a4*Ws[256+c] + a5*Ws[320+c];
        Hs[r][c] = fmaxf(h, 0.f);
    }
    __syncthreads();
    if (t < 64) {
        float s = 0.f, sq = 0.f;
        for (int c = 0; c < 64; c++) { float v = Hs[t][c]; s += v; sq += v * v; }
        float m = s * (1.f / 64.f);
        mu[t] = m; rs[t] = rsqrtf(sq * (1.f / 64.f) - m * m + 1e-5f);
    }
    __syncthreads();
    for (int i = t; i < 4096; i += 256) {
        int rr = i >> 6, c = i & 63;
        out[(size_t)ebase * 64 + i] = (Hs[rr][c] - mu[rr]) * rs[rr] * Gs[c] + BEs[c];
    }
}

// ======= msg MLP + fused scatter-add: 128 edges/block, 4x8 per thread ========
__global__ void __launch_bounds__(256, 2) k_msg(const float* __restrict__ node,
    const float* __restrict__ edge, const int* __restrict__ ei,
    const float* __restrict__ w1, const float* __restrict__ b1,
    const float* __restrict__ w2, const float* __restrict__ b2, float* __restrict__ agg) {
    extern __shared__ float sm[];
    float* W1s = sm;           // 12288
    float* W2s = W1s + 12288;  // 4096
    float* B1s = W2s + 4096; float* B2s = B1s + 64;
    float* As = B2s + 64;      // 128*65 (reused for H)
    int* srcs = (int*)(As + 8320);
    int* dsts = srcs + 128;
    const int t = threadIdx.x;
    const int ebase = blockIdx.x * 128;
    for (int i = t; i < 12288; i += 256) W1s[i] = w1[i];
    for (int i = t; i < 4096; i += 256) W2s[i] = w2[i];
    if (t < 64) { B1s[t]=b1[t]; B2s[t]=b2[t]; }
    if (t < 128) { srcs[t] = ei[ebase + t]; dsts[t] = ei[EE + ebase + t]; }
    const int tr = t >> 3, tc = t & 7;
    const float* ar[4];
    #pragma unroll
    for (int i = 0; i < 4; i++) ar[i] = &As[(tr * 4 + i) * 65];
    float acc[4][8];
    for (int ch = 0; ch < 3; ch++) {
        __syncthreads();
        for (int e = t * 4; e < 8192; e += 1024) {
            int row = e >> 6, c4 = e & 63;
            const float* base = (ch == 0) ? &node[(size_t)dsts[row] * 64]
                              : (ch == 1) ? &node[(size_t)srcs[row] * 64]
                                          : &edge[(size_t)(ebase + row) * 64];
            float4 vv = *(const float4*)&base[c4];
            float* d = &As[row * 65 + c4];
            d[0]=vv.x; d[1]=vv.y; d[2]=vv.z; d[3]=vv.w;
        }
        __syncthreads();
        if (ch == 0) {
            float4 ba = *(const float4*)&B1s[tc * 8];
            float4 bb = *(const float4*)&B1s[tc * 8 + 4];
            #pragma unroll
            for (int i = 0; i < 4; i++) {
                acc[i][0]=ba.x;acc[i][1]=ba.y;acc[i][2]=ba.z;acc[i][3]=ba.w;
                acc[i][4]=bb.x;acc[i][5]=bb.y;acc[i][6]=bb.z;acc[i][7]=bb.w;
            }
        }
        const float* wp = &W1s[ch * 4096 + tc * 8];
        #pragma unroll 8
        for (int k = 0; k < 64; k++) {
            float4 wa = *(const float4*)&wp[k * 64];
            float4 wb = *(const float4*)&wp[k * 64 + 4];
            #pragma unroll
            for (int i = 0; i < 4; i++) {
                float a = ar[i][k];
                acc[i][0]+=a*wa.x; acc[i][1]+=a*wa.y; acc[i][2]+=a*wa.z; acc[i][3]+=a*wa.w;
                acc[i][4]+=a*wb.x; acc[i][5]+=a*wb.y; acc[i][6]+=a*wb.z; acc[i][7]+=a*wb.w;
            }
        }
    }
    __syncthreads();
    #pragma unroll
    for (int i = 0; i < 4; i++)
        #pragma unroll
        for (int j = 0; j < 8; j++)
            As[(tr * 4 + i) * 65 + tc * 8 + j] = fmaxf(acc[i][j], 0.f);
    __syncthreads();
    float a2[4][8];
    {
        float4 ba = *(const float4*)&B2s[tc * 8];
        float4 bb = *(const float4*)&B2s[tc * 8 + 4];
        #pragma unroll
        for (int i = 0; i < 4; i++) {
            a2[i][0]=ba.x;a2[i][1]=ba.y;a2[i][2]=ba.z;a2[i][3]=ba.w;
            a2[i][4]=bb.x;a2[i][5]=bb.y;a2[i][6]=bb.z;a2[i][7]=bb.w;
        }
    }
    const float* wp2 = &W2s[tc * 8];
    #pragma unroll 8
    for (int k = 0; k < 64; k++) {
        float4 wa = *(const float4*)&wp2[k * 64];
        float4 wb = *(const float4*)&wp2[k * 64 + 4];
        #pragma unroll
        for (int i = 0; i < 4; i++) {
            float a = ar[i][k];
            a2[i][0]+=a*wa.x; a2[i][1]+=a*wa.y; a2[i][2]+=a*wa.z; a2[i][3]+=a*wa.w;
            a2[i][4]+=a*wb.x; a2[i][5]+=a*wb.y; a2[i][6]+=a*wb.z; a2[i][7]+=a*wb.w;
        }
    }
    #pragma unroll
    for (int i = 0; i < 4; i++) {
        int d = dsts[tr * 4 + i];
        float* ap = &agg[(size_t)d * 64 + tc * 8];
        #pragma unroll
        for (int j = 0; j < 8; j++) atomicAdd(ap + j, a2[i][j]);
    }
}

// ========= node MLP: [node|agg] 2-layer, 128 nodes/block, 4x8 per thread =====
__global__ void __launch_bounds__(256, 2) k_nodemlp(const float* __restrict__ node,
    const float* __restrict__ agg, const float* __restrict__ w1, const float* __restrict__ b1,
    const float* __restrict__ w2, const float* __restrict__ b2, float* __restrict__ out) {
    extern __shared__ float sm[];
    float* W1s = sm;           // 8192
    float* W2s = W1s + 8192;   // 4096
    float* B1s = W2s + 4096; float* B2s = B1s + 64;
    float* As = B2s + 64;      // 128*65 (reused for H)
    const int t = threadIdx.x;
    const int Rbase = blockIdx.x * 128;
    for (int i = t; i < 8192; i += 256) W1s[i] = w1[i];
    for (int i = t; i < 4096; i += 256) W2s[i] = w2[i];
    if (t < 64) { B1s[t]=b1[t]; B2s[t]=b2[t]; }
    const int tr = t >> 3, tc = t & 7;
    const float* ar[4];
    #pragma unroll
    for (int i = 0; i < 4; i++) ar[i] = &As[(tr * 4 + i) * 65];
    float acc[4][8];
    for (int ch = 0; ch < 2; ch++) {
        __syncthreads();
        for (int e = t * 4; e < 8192; e += 1024) {
            int row = e >> 6, c4 = e & 63, nd = Rbase + row;
            float4 vv = make_float4(0.f,0.f,0.f,0.f);
            if (nd < NN) {
                const float* base = (ch == 0) ? &node[(size_t)nd * 64] : &agg[(size_t)nd * 64];
                vv = *(const float4*)&base[c4];
            }
            float* d = &As[row * 65 + c4];
            d[0]=vv.x; d[1]=vv.y; d[2]=vv.z; d[3]=vv.w;
        }
        __syncthreads();
        if (ch == 0) {
            float4 ba = *(const float4*)&B1s[tc * 8];
            float4 bb = *(const float4*)&B1s[tc * 8 + 4];
            #pragma unroll
            for (int i = 0; i < 4; i++) {
                acc[i][0]=ba.x;acc[i][1]=ba.y;acc[i][2]=ba.z;acc[i][3]=ba.w;
                acc[i][4]=bb.x;acc[i][5]=bb.y;acc[i][6]=bb.z;acc[i][7]=bb.w;
            }
        }
        const float* wp = &W1s[ch * 4096 + tc * 8];
        #pragma unroll 8
        for (int k = 0; k < 64; k++) {
            float4 wa = *(const float4*)&wp[k * 64];
            float4 wb = *(const float4*)&wp[k * 64 + 4];
            #pragma unroll
            for (int i = 0; i < 4; i++) {
                float a = ar[i][k];
                acc[i][0]+=a*wa.x; acc[i][1]+=a*wa.y; acc[i][2]+=a*wa.z; acc[i][3]+=a*wa.w;
                acc[i][4]+=a*wb.x; acc[i][5]+=a*wb.y; acc[i][6]+=a*wb.z; acc[i][7]+=a*wb.w;
            }
        }
    }
    __syncthreads();
    #pragma unroll
    for (int i = 0; i < 4; i++)
        #pragma unroll
        for (int j = 0; j < 8; j++)
            As[(tr * 4 + i) * 65 + tc * 8 + j] = fmaxf(acc[i][j], 0.f);
    __syncthreads();
    float a2[4][8];
    {
        float4 ba = *(const float4*)&B2s[tc * 8];
        float4 bb = *(const float4*)&B2s[tc * 8 + 4];
        #pragma unroll
        for (int i = 0; i < 4; i++) {
            a2[i][0]=ba.x;a2[i][1]=ba.y;a2[i][2]=ba.z;a2[i][3]=ba.w;
            a2[i][4]=bb.x;a2[i][5]=bb.y;a2[i][6]=bb.z;a2[i][7]=bb.w;
        }
    }
    const float* wp2 = &W2s[tc * 8];
    #pragma unroll 8
    for (int k = 0; k < 64; k++) {
        float4 wa = *(const float4*)&wp2[k * 64];
        float4 wb = *(const float4*)&wp2[k * 64 + 4];
        #pragma unroll
        for (int i = 0; i < 4; i++) {
            float a = ar[i][k];
            a2[i][0]+=a*wa.x; a2[i][1]+=a*wa.y; a2[i][2]+=a*wa.z; a2[i][3]+=a*wa.w;
            a2[i][4]+=a*wb.x; a2[i][5]+=a*wb.y; a2[i][6]+=a*wb.z; a2[i][7]+=a*wb.w;
        }
    }
    #pragma unroll
    for (int i = 0; i < 4; i++) {
        int nd = Rbase + tr * 4 + i;
        if (nd < NN) {
            float4 v;
            v.x=a2[i][0]; v.y=a2[i][1]; v.z=a2[i][2]; v.w=a2[i][3];
            *(float4*)&out[(size_t)nd * 64 + tc * 8] = v;
            v.x=a2[i][4]; v.y=a2[i][5]; v.z=a2[i][6]; v.w=a2[i][7];
            *(float4*)&out[(size_t)nd * 64 + tc * 8 + 4] = v;
        }
    }
}

// --------------------------------------------- final edge MLP: 134->128->64->1
__global__ void __launch_bounds__(256) k_final(const float* __restrict__ node,
    const float* __restrict__ ea, const int* __restrict__ ei,
    const float* __restrict__ w1, const float* __restrict__ b1,
    const float* __restrict__ w2, const float* __restrict__ b2,
    const float* __restrict__ w3, const float* __restrict__ b3, float* __restrict__ out) {
    extern __shared__ float sm[];
    float* W1s = sm;              // 17152
    float* B1s = W1s + 17152;     // 128
    float* W2s = B1s + 128;       // 8192
    float* B2s = W2s + 8192;      // 64
    float* w3s = B2s + 64;        // 64
    float* b3s = w3s + 64;        // 4
    float* As  = b3s + 4;         // 64*68
    float* Hs  = As + 4352;       // 64*132
    float* H2s = Hs + 8448;       // 64*68
    int* srcs = (int*)(H2s + 4352);
    int* dsts = srcs + 64;
    int t = threadIdx.x;
    int ebase = blockIdx.x * 64;
    for (int i = t; i < 17152; i += 256) W1s[i] = w1[i];
    for (int i = t; i < 8192; i += 256) W2s[i] = w2[i];
    if (t < 128) B1s[t] = b1[t];
    if (t < 64) { B2s[t]=b2[t]; w3s[t]=w3[t]; srcs[t]=ei[ebase+t]; dsts[t]=ei[EE+ebase+t]; }
    if (t == 0) b3s[0] = b3[0];
    int tr = t >> 4, tc = t & 15;
    float acc[4][8];
    for (int ch = 0; ch < 2; ch++) {
        __syncthreads();
        for (int e = t * 4; e < 4096; e += 1024) {
            int row = e >> 6, c4 = e & 63;
            const float* base = (ch == 0) ? &node[(size_t)srcs[row] * 64]
                                          : &node[(size_t)dsts[row] * 64];
            *(float4*)&As[row * 68 + c4] = *(const float4*)&base[c4];
        }
        __syncthreads();
        if (ch == 0) {
            #pragma unroll
            for (int i = 0; i < 4; i++)
                #pragma unroll
                for (int j = 0; j < 8; j++) acc[i][j] = B1s[tc * 8 + j];
        }
        for (int k = 0; k < 64; k++) {
            float4 wa = *(const float4*)&W1s[(ch * 64 + k) * 128 + tc * 8];
            float4 wb = *(const float4*)&W1s[(ch * 64 + k) * 128 + tc * 8 + 4];
            #pragma unroll
            for (int i = 0; i < 4; i++) {
                float a = As[(tr * 4 + i) * 68 + k];
                acc[i][0]+=a*wa.x; acc[i][1]+=a*wa.y; acc[i][2]+=a*wa.z; acc[i][3]+=a*wa.w;
                acc[i][4]+=a*wb.x; acc[i][5]+=a*wb.y; acc[i][6]+=a*wb.z; acc[i][7]+=a*wb.w;
            }
        }
    }
    __syncthreads();
    for (int e = t; e < 384; e += 256) {
        int row = e / 6, k = e - row * 6;
        As[row * 8 + k] = ea[(size_t)(ebase + row) * 6 + k];
    }
    __syncthreads();
    for (int k = 0; k < 6; k++) {
        float4 wa = *(const float4*)&W1s[(128 + k) * 128 + tc * 8];
        float4 wb = *(const float4*)&W1s[(128 + k) * 128 + tc * 8 + 4];
        #pragma unroll
        for (int i = 0; i < 4; i++) {
            float a = As[(tr * 4 + i) * 8 + k];
            acc[i][0]+=a*wa.x; acc[i][1]+=a*wa.y; acc[i][2]+=a*wa.z; acc[i][3]+=a*wa.w;
            acc[i][4]+=a*wb.x; acc[i][5]+=a*wb.y; acc[i][6]+=a*wb.z; acc[i][7]+=a*wb.w;
        }
    }
    #pragma unroll
    for (int i = 0; i < 4; i++)
        #pragma unroll
        for (int j = 0; j < 8; j++)
            Hs[(tr * 4 + i) * 132 + tc * 8 + j] = fmaxf(acc[i][j], 0.f);
    __syncthreads();
    float a2[4][4];
    #pragma unroll
    for (int i = 0; i < 4; i++)
        #pragma unroll
        for (int j = 0; j < 4; j++) a2[i][j] = B2s[tc * 4 + j];
    for (int k = 0; k < 128; k++) {
        float4 w4 = *(const float4*)&W2s[k * 64 + tc * 4];
        #pragma unroll
        for (int i = 0; i < 4; i++) {
            float a = Hs[(tr * 4 + i) * 132 + k];
            a2[i][0] += a*w4.x; a2[i][1] += a*w4.y; a2[i][2] += a*w4.z; a2[i][3] += a*w4.w;
        }
    }
    #pragma unroll
    for (int i = 0; i < 4; i++)
        #pragma unroll
        for (int j = 0; j < 4; j++)
            H2s[(tr * 4 + i) * 68 + tc * 4 + j] = fmaxf(a2[i][j], 0.f);
    __syncthreads();
    if (t < 64) {
        float s = b3s[0];
        for (int c = 0; c < 64; c++) s += H2s[t * 68 + c] * w3s[c];
        out[ebase + t] = s;
    }
}

// ============================================================================
extern "C" void kernel_launch(void* const* d_in, const int* in_sizes, int n_in,
                              void* d_out, int out_size) {
    const float *x=0,*ea=0,*crop=0,*cw0=0,*cb0=0,*cw=0,*cb=0,*nu_w=0,*nu_b=0,*nu_g=0,*nu_be=0,
        *eu_w=0,*eu_b=0,*eu_g=0,*eu_be=0,*ie_w1=0,*ie_b1=0,*ie_w2=0,*ie_b2=0,
        *in_w1=0,*in_b1=0,*in_w2=0,*in_b2=0,*em_w1=0,*em_b1=0,*em_w2=0,*em_b2=0,*em_w3=0,*em_b3=0;
    const int* ei = 0;
    int c64 = 0, c256 = 0, c16k = 0;
    for (int i = 0; i < n_in; i++) {
        const float* p = (const float*)d_in[i];
        switch (in_sizes[i]) {
            case 320000: x = p; break;
            case 640000: ei = (const int*)p; break;
            case 1920000: ea = p; break;
            case 122880000: crop = p; break;
            case 768: cw0 = p; break;
            case 81920: cw = p; break;
            case 320: cb = p; break;
            case 6144: nu_w = p; break;
            case 384: eu_w = p; break;
            case 49152: ie_w1 = p; break;
            case 32768: in_w1 = p; break;
            case 17152: em_w1 = p; break;
            case 128: em_b1 = p; break;
            case 8192: em_w2 = p; break;
            case 1: em_b3 = p; break;
            case 16384: if (c16k++ == 0) ie_w2 = p; else in_w2 = p; break;
            case 256:
                if (c256 == 0) ie_b1 = p; else if (c256 == 1) ie_b2 = p;
                else if (c256 == 2) in_b1 = p; else in_b2 = p;
                c256++; break;
            case 64: {
                const float** slots[9] = {&cb0,&nu_b,&nu_g,&nu_be,&eu_b,&eu_g,&eu_be,&em_b2,&em_w3};
                if (c64 < 9) *slots[c64] = p;
                c64++; break;
            }
            default: break;
        }
    }
    float *b0, *b1, *cf, *nA, *nB, *agg, *edg;
    cudaGetSymbolAddress((void**)&b0, g_b0);
    cudaGetSymbolAddress((void**)&b1, g_b1);
    cudaGetSymbolAddress((void**)&cf, g_cf);
    cudaGetSymbolAddress((void**)&nA, g_nA);
    cudaGetSymbolAddress((void**)&nB, g_nB);
    cudaGetSymbolAddress((void**)&agg, g_agg);
    cudaGetSymbolAddress((void**)&edg, g_edge);

    const int SM01   = (768 + 64 + 16384 + 64 + 3168 + 16640) * 4;
    const int SM_CONV = (16384 + 64 + 128 * 65) * 4;
    const int SM_NU   = (6144 + 64 * 5 + 6400 + 4352 + 64) * 4;
    const int SM_MSG  = (12288 + 4096 + 128 + 8320) * 4 + 256 * 4;
    const int SM_NM   = (8192 + 4096 + 128 + 8320) * 4;
    const int SM_FIN  = (17152 + 128 + 8192 + 64 + 64 + 4 + 4352 + 8448 + 4352) * 4 + 512;
    cudaFuncSetAttribute(k_conv01,  cudaFuncAttributeMaxDynamicSharedMemorySize, SM01);
    cudaFuncSetAttribute(k_conv,    cudaFuncAttributeMaxDynamicSharedMemorySize, SM_CONV);
    cudaFuncSetAttribute(k_nodeup,  cudaFuncAttributeMaxDynamicSharedMemorySize, SM_NU);
    cudaFuncSetAttribute(k_msg,     cudaFuncAttributeMaxDynamicSharedMemorySize, SM_MSG);
    cudaFuncSetAttribute(k_nodemlp, cudaFuncAttributeMaxDynamicSharedMemorySize, SM_NM);
    cudaFuncSetAttribute(k_final,   cudaFuncAttributeMaxDynamicSharedMemorySize, SM_FIN);

    // CNN stack
    k_conv01<<<40000, 256, SM01>>>(crop, cw0, cb0, cw, cb, b1);
    k_conv<<<5000, 256, SM_CONV>>>(b1, b0, cw + 16384, cb + 64,  3, NN * 64);
    k_conv<<<1250, 256, SM_CONV>>>(b0, b1, cw + 32768, cb + 128, 2, NN * 16);
    k_conv<<<313,  256, SM_CONV>>>(b1, b0, cw + 49152, cb + 192, 1, NN * 4);
    k_conv<<<79,   256, SM_CONV>>>(b0, cf, cw + 65536, cb + 256, 0, NN);
    // encoders
    k_nodeup<<<157, 256, SM_NU>>>(x, cf, nu_w, nu_b, nu_g, nu_be, nA);
    k_edgeup<<<5000, 256>>>(ea, eu_w, eu_b, eu_g, eu_be, edg);
    // 4 interaction layers
    float* cur = nA; float* nxt = nB;
    for (int l = 0; l < 4; l++) {
        cudaMemsetAsync(agg, 0, (size_t)NN * 64 * sizeof(float), 0);
        k_msg<<<2500, 256, SM_MSG>>>(cur, edg, ei, ie_w1 + l * 12288, ie_b1 + l * 64,
                                     ie_w2 + l * 4096, ie_b2 + l * 64, agg);
        k_nodemlp<<<79, 256, SM_NM>>>(cur, agg, in_w1 + l * 8192, in_b1 + l * 64,
                                      in_w2 + l * 4096, in_b2 + l * 64, nxt);
        float* tmp = cur; cur = nxt; nxt = tmp;
    }
    // final edge MLP
    k_final<<<5000, 256, SM_FIN>>>(cur, ea, ei, em_w1, em_b1, em_w2, em_b2,
                                   em_w3, em_b3, (float*)d_out);
}